// round 13
// baseline (speedup 1.0000x reference)
#include <cuda_runtime.h>

#define NJ   24
#define TPB  192
#define NPB  (TPB * 2)     // 384 nodes = 16 frames per block; thread owns nodes t, t+192
#define RS   28            // sH row stride (floats): h[24] + a_src[3] + pad
#define NEG  0.2f

typedef unsigned long long ull;

__constant__ int c_parent[NJ] = {-1,0,0,0,1,2,3,4,5,6,7,8,9,9,9,12,13,14,16,17,18,19,20,21};
#define PARENT_MASK 0x3F73FFu   // joints that are some child's parent

// Parameters staged into the constant bank per launch (D2D memcpy nodes)
__constant__ __align__(16) float cWg[576];    // (24,24)
__constant__ __align__(16) float cWpre[72];   // (3,24)
__constant__ __align__(16) float cbpre[24];
__constant__ __align__(16) float cAttS[24];
__constant__ __align__(16) float cAttD[24];
__constant__ __align__(16) float cbg[24];

__device__ __forceinline__ void fma2(ull &d, ull a, ull b) {
    asm("fma.rn.f32x2 %0, %1, %2, %0;" : "+l"(d) : "l"(a), "l"(b));
}
__device__ __forceinline__ ull pack2(float x) {
    ull r; asm("mov.b64 %0, {%1, %1};" : "=l"(r) : "f"(x)); return r;
}
__device__ __forceinline__ ull packf2(float lo, float hi) {
    ull r; asm("mov.b64 %0, {%1, %2};" : "=l"(r) : "f"(lo), "f"(hi)); return r;
}
__device__ __forceinline__ float2 unpack2(ull v) {
    float2 f; asm("mov.b64 {%0, %1}, %2;" : "=f"(f.x), "=f"(f.y) : "l"(v)); return f;
}

// epilogue for one node: 2-edge softmax + aggregate + bias + relu + store
__device__ __forceinline__ void finish_node(const ull* __restrict__ acc,   // 12 ch-pairs
                                            const float* __restrict__ aS,  // [3]
                                            const float* __restrict__ aD,  // [3]
                                            const float* __restrict__ prow,
                                            bool hasPar,
                                            const ull* __restrict__ bgp,   // 12 bias pairs
                                            float* __restrict__ outp)
{
    const ulonglong2* p2 = (const ulonglong2*)prow;
    ulonglong2 pr[6];
    #pragma unroll
    for (int q = 0; q < 6; q++) pr[q] = p2[q];         // parent h as 12 ch-pairs
    const float pasv[3] = {prow[24], prow[25], prow[26]};

    float alS[3], alP[3];
    #pragma unroll
    for (int hh = 0; hh < 3; hh++) {
        float es = aS[hh] + aD[hh];
        es = es >= 0.0f ? es : NEG * es;
        float ep = pasv[hh] + aD[hh];
        ep = ep >= 0.0f ? ep : NEG * ep;
        ep = hasPar ? ep : -1e30f;
        const float mx  = fmaxf(es, ep);
        const float ws  = __expf(es - mx);
        const float wp  = __expf(ep - mx);
        const float inv = __fdividef(1.0f, ws + wp);
        alS[hh] = ws * inv;
        alP[hh] = hasPar ? wp * inv : 0.0f;
    }

    float4* o4 = (float4*)outp;
    #pragma unroll
    for (int v = 0; v < 6; v++) {                       // 2 ch-pairs per float4
        const int q0 = 2*v, q1 = 2*v + 1;
        const int hh = v >> 1;
        const ull s2 = pack2(alS[hh]);
        const ull p2k = pack2(alP[hh]);
        ull o0 = bgp[q0], o1 = bgp[q1];
        const ull ph0 = (q0 & 1) ? pr[q0 >> 1].y : pr[q0 >> 1].x;
        const ull ph1 = (q1 & 1) ? pr[q1 >> 1].y : pr[q1 >> 1].x;
        fma2(o0, s2, acc[q0]); fma2(o0, p2k, ph0);
        fma2(o1, s2, acc[q1]); fma2(o1, p2k, ph1);
        const float2 f0 = unpack2(o0), f1 = unpack2(o1);
        float4 r;
        r.x = fmaxf(f0.x, 0.f); r.y = fmaxf(f0.y, 0.f);
        r.z = fmaxf(f1.x, 0.f); r.w = fmaxf(f1.y, 0.f);
        o4[v] = r;
    }
}

__global__ __launch_bounds__(TPB, 4)
void gat_encoder_kernel(const float* __restrict__ src,
                        const float* __restrict__ Wg,     // (24,24) for shared staging
                        float* __restrict__ out)
{
    __shared__ __align__(16) float sWgL[24 * 12]; // Wg channels 0..11, 48B rows
    __shared__ __align__(16) float sH[NPB * RS];

    const int t = threadIdx.x;
    const int j = t % NJ;

    for (int i = t; i < 288; i += TPB) {
        const int row = i / 12, c = i % 12;
        sWgL[i] = Wg[row * 24 + c];
    }

    const size_t base = (size_t)blockIdx.x * NPB;

    // ---- inputs: node pair (t, t+192) packed per input channel ----
    const float* pA = src + (base + (size_t)t) * 3;
    const float* pB = src + (base + (size_t)(t + TPB)) * 3;
    const float a0 = pA[0], a1 = pA[1], a2 = pA[2];
    const float b0 = pB[0], b1 = pB[1], b2 = pB[2];
    const ull pin0 = packf2(a0, b0);
    const ull pin1 = packf2(a1, b1);
    const ull pin2 = packf2(a2, b2);

    __syncthreads();

    // ---- fused: per k, x[k] for both nodes (one packed fma chain), feed 24-ch GEMM ----
    ull accA[12], accB[12];   // channel pairs for node t / node t+192
    #pragma unroll
    for (int q = 0; q < 12; q++) { accA[q] = 0ull; accB[q] = 0ull; }

    #pragma unroll
    for (int k = 0; k < 24; k++) {
        // x-chain weights from the constant bank (uniform)
        ull xc = pack2(cbpre[k]);                      // bias pair
        fma2(xc, pin0, pack2(cWpre[k]));
        fma2(xc, pin1, pack2(cWpre[24 + k]));
        fma2(xc, pin2, pack2(cWpre[48 + k]));
        const float2 f = unpack2(xc);
        const ull xi = pack2(fmaxf(f.x, 0.0f));        // node t
        const ull xj = pack2(fmaxf(f.y, 0.0f));        // node t+192

        // channels 0..11 from shared (3 LDS.128)
        const ulonglong2* wr = (const ulonglong2*)(sWgL + k * 12);
        const ulonglong2 w0 = wr[0], w1 = wr[1], w2 = wr[2];
        // channels 12..23 from constant cache (3 LDC.128, off the L1 port)
        const ulonglong2 w3 = *(const ulonglong2*)(cWg + k * 24 + 12);
        const ulonglong2 w4 = *(const ulonglong2*)(cWg + k * 24 + 16);
        const ulonglong2 w5 = *(const ulonglong2*)(cWg + k * 24 + 20);

        fma2(accA[0], xi, w0.x); fma2(accA[1], xi, w0.y);
        fma2(accA[2], xi, w1.x); fma2(accA[3], xi, w1.y);
        fma2(accB[0], xj, w0.x); fma2(accB[1], xj, w0.y);
        fma2(accB[2], xj, w1.x); fma2(accB[3], xj, w1.y);
        fma2(accA[4], xi, w2.x); fma2(accA[5], xi, w2.y);
        fma2(accA[6], xi, w3.x); fma2(accA[7], xi, w3.y);
        fma2(accB[4], xj, w2.x); fma2(accB[5], xj, w2.y);
        fma2(accB[6], xj, w3.x); fma2(accB[7], xj, w3.y);
        fma2(accA[8],  xi, w4.x); fma2(accA[9],  xi, w4.y);
        fma2(accA[10], xi, w5.x); fma2(accA[11], xi, w5.y);
        fma2(accB[8],  xj, w4.x); fma2(accB[9],  xj, w4.y);
        fma2(accB[10], xj, w5.x); fma2(accB[11], xj, w5.y);
    }

    // ---- attention dots, all 3 heads, both nodes (att vectors from constant) ----
    float aSA[3], aDA[3], aSB[3], aDB[3];
    {
        #pragma unroll
        for (int hh = 0; hh < 3; hh++) {
            const ulonglong2 sa = *(const ulonglong2*)(cAttS + 8*hh);
            const ulonglong2 sb = *(const ulonglong2*)(cAttS + 8*hh + 4);
            const ulonglong2 da = *(const ulonglong2*)(cAttD + 8*hh);
            const ulonglong2 db = *(const ulonglong2*)(cAttD + 8*hh + 4);
            ull rSA = 0ull, rDA = 0ull, rSB = 0ull, rDB = 0ull;
            fma2(rSA, accA[4*hh],   sa.x); fma2(rSA, accA[4*hh+1], sa.y);
            fma2(rSA, accA[4*hh+2], sb.x); fma2(rSA, accA[4*hh+3], sb.y);
            fma2(rDA, accA[4*hh],   da.x); fma2(rDA, accA[4*hh+1], da.y);
            fma2(rDA, accA[4*hh+2], db.x); fma2(rDA, accA[4*hh+3], db.y);
            fma2(rSB, accB[4*hh],   sa.x); fma2(rSB, accB[4*hh+1], sa.y);
            fma2(rSB, accB[4*hh+2], sb.x); fma2(rSB, accB[4*hh+3], sb.y);
            fma2(rDB, accB[4*hh],   da.x); fma2(rDB, accB[4*hh+1], da.y);
            fma2(rDB, accB[4*hh+2], db.x); fma2(rDB, accB[4*hh+3], db.y);
            float2 f;
            f = unpack2(rSA); aSA[hh] = f.x + f.y;
            f = unpack2(rDA); aDA[hh] = f.x + f.y;
            f = unpack2(rSB); aSB[hh] = f.x + f.y;
            f = unpack2(rDB); aDB[hh] = f.x + f.y;
        }
    }

    // ---- publish h + a_src (only parent joints) ----
    if ((PARENT_MASK >> j) & 1u) {
        ulonglong2* r0 = (ulonglong2*)(sH + t * RS);
        ulonglong2* r1 = (ulonglong2*)(sH + (t + TPB) * RS);
        #pragma unroll
        for (int q = 0; q < 6; q++) {
            ulonglong2 va; va.x = accA[2*q]; va.y = accA[2*q + 1]; r0[q] = va;
            ulonglong2 vb; vb.x = accB[2*q]; vb.y = accB[2*q + 1]; r1[q] = vb;
        }
        float* f0 = sH + t * RS;
        float* f1 = sH + (t + TPB) * RS;
        f0[24] = aSA[0]; f0[25] = aSA[1]; f0[26] = aSA[2];
        f1[24] = aSB[0]; f1[25] = aSB[1]; f1[26] = aSB[2];
    }
    __syncthreads();

    // ---- epilogue ----
    const int par = c_parent[j];
    const bool hasPar = (par >= 0);
    const int pt = (t - j) + (hasPar ? par : j);

    ull bgp[12];
    {
        #pragma unroll
        for (int v = 0; v < 6; v++) {
            const ulonglong2 b2 = *(const ulonglong2*)(cbg + 4*v);
            bgp[2*v] = b2.x; bgp[2*v + 1] = b2.y;
        }
    }

    finish_node(accA, aSA, aDA, sH + pt * RS,         hasPar, bgp, out + (base + (size_t)t) * 24);
    finish_node(accB, aSB, aDB, sH + (pt + TPB) * RS, hasPar, bgp, out + (base + (size_t)(t + TPB)) * 24);
}

extern "C" void kernel_launch(void* const* d_in, const int* in_sizes, int n_in,
                              void* d_out, int out_size) {
    (void)n_in; (void)out_size;
    const float* src  = (const float*)d_in[0];
    const float* Wpre = (const float*)d_in[1];
    const float* bpre = (const float*)d_in[2];
    const float* Wg   = (const float*)d_in[3];
    const float* attS = (const float*)d_in[4];
    const float* attD = (const float*)d_in[5];
    const float* bg   = (const float*)d_in[6];

    // Stage all parameters into the constant bank (D2D memcpy nodes; capture-legal)
    cudaMemcpyToSymbolAsync(cWg,   Wg,   576 * sizeof(float), 0, cudaMemcpyDeviceToDevice, 0);
    cudaMemcpyToSymbolAsync(cWpre, Wpre,  72 * sizeof(float), 0, cudaMemcpyDeviceToDevice, 0);
    cudaMemcpyToSymbolAsync(cbpre, bpre,  24 * sizeof(float), 0, cudaMemcpyDeviceToDevice, 0);
    cudaMemcpyToSymbolAsync(cAttS, attS,  24 * sizeof(float), 0, cudaMemcpyDeviceToDevice, 0);
    cudaMemcpyToSymbolAsync(cAttD, attD,  24 * sizeof(float), 0, cudaMemcpyDeviceToDevice, 0);
    cudaMemcpyToSymbolAsync(cbg,   bg,    24 * sizeof(float), 0, cudaMemcpyDeviceToDevice, 0);

    const int nodes  = in_sizes[0] / 3;   // 3,145,728
    const int blocks = nodes / NPB;       // 8,192 (exact)

    gat_encoder_kernel<<<blocks, TPB>>>(src, Wg, (float*)d_out);
}

// round 14
// speedup vs baseline: 1.0424x; 1.0424x over previous
#include <cuda_runtime.h>

#define NJ   24
#define TPB  192
#define NPB  (TPB * 2)     // 384 nodes = 16 frames per block; thread owns nodes t, t+192
#define RS   28            // sH row stride (floats): h[24] + a_src[3] + pad
#define NEG  0.2f

typedef unsigned long long ull;

__constant__ int c_parent[NJ] = {-1,0,0,0,1,2,3,4,5,6,7,8,9,9,9,12,13,14,16,17,18,19,20,21};
#define PARENT_MASK 0x3F73FFu   // joints that are some child's parent

// Packed parameter block layout (floats):
//  [0..191]   per-k x-chain table: {w0,w0},{w1,w1},{w2,w2},{b,b}  (8 per k, 24 k)
//  [192..767] Wg (24x24) row-major
//  [768..791] attS   [792..815] attD   [816..839] bg
__constant__ __align__(16) float cPack[840];
__device__   __align__(16) float dPack[840];   // staging (written by pack kernel)

__device__ __forceinline__ void fma2(ull &d, ull a, ull b) {
    asm("fma.rn.f32x2 %0, %1, %2, %0;" : "+l"(d) : "l"(a), "l"(b));
}
__device__ __forceinline__ ull pack2(float x) {
    ull r; asm("mov.b64 %0, {%1, %1};" : "=l"(r) : "f"(x)); return r;
}
__device__ __forceinline__ ull packf2(float lo, float hi) {
    ull r; asm("mov.b64 %0, {%1, %2};" : "=l"(r) : "f"(lo), "f"(hi)); return r;
}
__device__ __forceinline__ float2 unpack2(ull v) {
    float2 f; asm("mov.b64 {%0, %1}, %2;" : "=f"(f.x), "=f"(f.y) : "l"(v)); return f;
}

__global__ void pack_params(const float* __restrict__ Wpre, const float* __restrict__ bpre,
                            const float* __restrict__ Wg,   const float* __restrict__ attS,
                            const float* __restrict__ attD, const float* __restrict__ bg)
{
    const int t = threadIdx.x;
    if (t < 96) {                       // pre-splatted x-chain table
        const int k = t >> 2, r = t & 3;
        const float v = (r < 3) ? Wpre[r * 24 + k] : bpre[k];
        dPack[8*k + 2*r]     = v;
        dPack[8*k + 2*r + 1] = v;
    }
    for (int i = t; i < 576; i += blockDim.x) dPack[192 + i] = Wg[i];
    if (t < 24) {
        dPack[768 + t] = attS[t];
        dPack[792 + t] = attD[t];
        dPack[816 + t] = bg[t];
    }
}

// epilogue for one node: 2-edge softmax + aggregate + bias + relu + store
__device__ __forceinline__ void finish_node(const ull* __restrict__ acc,   // 12 ch-pairs
                                            const float* __restrict__ aS,  // [3]
                                            const float* __restrict__ aD,  // [3]
                                            const float* __restrict__ prow,
                                            bool hasPar,
                                            const ull* __restrict__ bgp,   // 12 bias pairs
                                            float* __restrict__ outp)
{
    const ulonglong2* p2 = (const ulonglong2*)prow;
    ulonglong2 pr[6];
    #pragma unroll
    for (int q = 0; q < 6; q++) pr[q] = p2[q];         // parent h as 12 ch-pairs
    const float pasv[3] = {prow[24], prow[25], prow[26]};

    float alS[3], alP[3];
    #pragma unroll
    for (int hh = 0; hh < 3; hh++) {
        float es = aS[hh] + aD[hh];
        es = es >= 0.0f ? es : NEG * es;
        float ep = pasv[hh] + aD[hh];
        ep = ep >= 0.0f ? ep : NEG * ep;
        ep = hasPar ? ep : -1e30f;
        const float mx  = fmaxf(es, ep);
        const float ws  = __expf(es - mx);
        const float wp  = __expf(ep - mx);
        const float inv = __fdividef(1.0f, ws + wp);
        alS[hh] = ws * inv;
        alP[hh] = hasPar ? wp * inv : 0.0f;
    }

    float4* o4 = (float4*)outp;
    #pragma unroll
    for (int v = 0; v < 6; v++) {                       // 2 ch-pairs per float4
        const int q0 = 2*v, q1 = 2*v + 1;
        const int hh = v >> 1;
        const ull s2 = pack2(alS[hh]);
        const ull p2k = pack2(alP[hh]);
        ull o0 = bgp[q0], o1 = bgp[q1];
        const ull ph0 = (q0 & 1) ? pr[q0 >> 1].y : pr[q0 >> 1].x;
        const ull ph1 = (q1 & 1) ? pr[q1 >> 1].y : pr[q1 >> 1].x;
        fma2(o0, s2, acc[q0]); fma2(o0, p2k, ph0);
        fma2(o1, s2, acc[q1]); fma2(o1, p2k, ph1);
        const float2 f0 = unpack2(o0), f1 = unpack2(o1);
        float4 r;
        r.x = fmaxf(f0.x, 0.f); r.y = fmaxf(f0.y, 0.f);
        r.z = fmaxf(f1.x, 0.f); r.w = fmaxf(f1.y, 0.f);
        o4[v] = r;
    }
}

__global__ __launch_bounds__(TPB, 4)
void gat_encoder_kernel(const float* __restrict__ src,
                        const float* __restrict__ Wg,     // (24,24) for shared staging
                        float* __restrict__ out)
{
    __shared__ __align__(16) float sWgL[24 * 12]; // Wg channels 0..11, 48B rows
    __shared__ __align__(16) float sH[NPB * RS];

    const int t = threadIdx.x;
    const int j = t % NJ;

    for (int i = t; i < 288; i += TPB) {
        const int row = i / 12, c = i % 12;
        sWgL[i] = Wg[row * 24 + c];
    }

    const size_t base = (size_t)blockIdx.x * NPB;

    // ---- inputs: node pair (t, t+192) packed per input channel ----
    const float* pA = src + (base + (size_t)t) * 3;
    const float* pB = src + (base + (size_t)(t + TPB)) * 3;
    const float a0 = pA[0], a1 = pA[1], a2 = pA[2];
    const float b0 = pB[0], b1 = pB[1], b2 = pB[2];
    const ull pin0 = packf2(a0, b0);
    const ull pin1 = packf2(a1, b1);
    const ull pin2 = packf2(a2, b2);

    __syncthreads();

    // ---- fused: per k, x[k] for both nodes (one packed fma chain), feed 24-ch GEMM ----
    ull accA[12], accB[12];   // channel pairs for node t / node t+192
    #pragma unroll
    for (int q = 0; q < 12; q++) { accA[q] = 0ull; accB[q] = 0ull; }

    #pragma unroll
    for (int k = 0; k < 24; k++) {
        // pre-splatted x-chain pairs from constant: 2 LDC.128
        const ulonglong2 q0 = *(const ulonglong2*)(cPack + 8*k);       // {w0,w0},{w1,w1}
        const ulonglong2 q1 = *(const ulonglong2*)(cPack + 8*k + 4);   // {w2,w2},{b,b}
        ull xc = q1.y;
        fma2(xc, pin0, q0.x);
        fma2(xc, pin1, q0.y);
        fma2(xc, pin2, q1.x);
        const float2 f = unpack2(xc);
        const ull xi = pack2(fmaxf(f.x, 0.0f));        // node t
        const ull xj = pack2(fmaxf(f.y, 0.0f));        // node t+192

        // channels 0..11 from shared (3 LDS.128)
        const ulonglong2* wr = (const ulonglong2*)(sWgL + k * 12);
        const ulonglong2 w0 = wr[0], w1 = wr[1], w2 = wr[2];
        // channels 12..23 from constant cache (3 LDC.128, off the L1 port)
        const ulonglong2 w3 = *(const ulonglong2*)(cPack + 192 + k * 24 + 12);
        const ulonglong2 w4 = *(const ulonglong2*)(cPack + 192 + k * 24 + 16);
        const ulonglong2 w5 = *(const ulonglong2*)(cPack + 192 + k * 24 + 20);

        fma2(accA[0], xi, w0.x); fma2(accA[1], xi, w0.y);
        fma2(accA[2], xi, w1.x); fma2(accA[3], xi, w1.y);
        fma2(accB[0], xj, w0.x); fma2(accB[1], xj, w0.y);
        fma2(accB[2], xj, w1.x); fma2(accB[3], xj, w1.y);
        fma2(accA[4], xi, w2.x); fma2(accA[5], xi, w2.y);
        fma2(accA[6], xi, w3.x); fma2(accA[7], xi, w3.y);
        fma2(accB[4], xj, w2.x); fma2(accB[5], xj, w2.y);
        fma2(accB[6], xj, w3.x); fma2(accB[7], xj, w3.y);
        fma2(accA[8],  xi, w4.x); fma2(accA[9],  xi, w4.y);
        fma2(accA[10], xi, w5.x); fma2(accA[11], xi, w5.y);
        fma2(accB[8],  xj, w4.x); fma2(accB[9],  xj, w4.y);
        fma2(accB[10], xj, w5.x); fma2(accB[11], xj, w5.y);
    }

    // ---- attention dots, all 3 heads, both nodes (att vectors from constant) ----
    float aSA[3], aDA[3], aSB[3], aDB[3];
    {
        #pragma unroll
        for (int hh = 0; hh < 3; hh++) {
            const ulonglong2 sa = *(const ulonglong2*)(cPack + 768 + 8*hh);
            const ulonglong2 sb = *(const ulonglong2*)(cPack + 768 + 8*hh + 4);
            const ulonglong2 da = *(const ulonglong2*)(cPack + 792 + 8*hh);
            const ulonglong2 db = *(const ulonglong2*)(cPack + 792 + 8*hh + 4);
            ull rSA = 0ull, rDA = 0ull, rSB = 0ull, rDB = 0ull;
            fma2(rSA, accA[4*hh],   sa.x); fma2(rSA, accA[4*hh+1], sa.y);
            fma2(rSA, accA[4*hh+2], sb.x); fma2(rSA, accA[4*hh+3], sb.y);
            fma2(rDA, accA[4*hh],   da.x); fma2(rDA, accA[4*hh+1], da.y);
            fma2(rDA, accA[4*hh+2], db.x); fma2(rDA, accA[4*hh+3], db.y);
            fma2(rSB, accB[4*hh],   sa.x); fma2(rSB, accB[4*hh+1], sa.y);
            fma2(rSB, accB[4*hh+2], sb.x); fma2(rSB, accB[4*hh+3], sb.y);
            fma2(rDB, accB[4*hh],   da.x); fma2(rDB, accB[4*hh+1], da.y);
            fma2(rDB, accB[4*hh+2], db.x); fma2(rDB, accB[4*hh+3], db.y);
            float2 f;
            f = unpack2(rSA); aSA[hh] = f.x + f.y;
            f = unpack2(rDA); aDA[hh] = f.x + f.y;
            f = unpack2(rSB); aSB[hh] = f.x + f.y;
            f = unpack2(rDB); aDB[hh] = f.x + f.y;
        }
    }

    // ---- publish h + a_src (only parent joints) ----
    if ((PARENT_MASK >> j) & 1u) {
        ulonglong2* r0 = (ulonglong2*)(sH + t * RS);
        ulonglong2* r1 = (ulonglong2*)(sH + (t + TPB) * RS);
        #pragma unroll
        for (int q = 0; q < 6; q++) {
            ulonglong2 va; va.x = accA[2*q]; va.y = accA[2*q + 1]; r0[q] = va;
            ulonglong2 vb; vb.x = accB[2*q]; vb.y = accB[2*q + 1]; r1[q] = vb;
        }
        float* f0 = sH + t * RS;
        float* f1 = sH + (t + TPB) * RS;
        f0[24] = aSA[0]; f0[25] = aSA[1]; f0[26] = aSA[2];
        f1[24] = aSB[0]; f1[25] = aSB[1]; f1[26] = aSB[2];
    }
    __syncthreads();

    // ---- epilogue ----
    const int par = c_parent[j];
    const bool hasPar = (par >= 0);
    const int pt = (t - j) + (hasPar ? par : j);

    ull bgp[12];
    {
        #pragma unroll
        for (int v = 0; v < 6; v++) {
            const ulonglong2 b2 = *(const ulonglong2*)(cPack + 816 + 4*v);
            bgp[2*v] = b2.x; bgp[2*v + 1] = b2.y;
        }
    }

    finish_node(accA, aSA, aDA, sH + pt * RS,         hasPar, bgp, out + (base + (size_t)t) * 24);
    finish_node(accB, aSB, aDB, sH + (pt + TPB) * RS, hasPar, bgp, out + (base + (size_t)(t + TPB)) * 24);
}

extern "C" void kernel_launch(void* const* d_in, const int* in_sizes, int n_in,
                              void* d_out, int out_size) {
    (void)n_in; (void)out_size;
    const float* src  = (const float*)d_in[0];
    const float* Wpre = (const float*)d_in[1];
    const float* bpre = (const float*)d_in[2];
    const float* Wg   = (const float*)d_in[3];
    const float* attS = (const float*)d_in[4];
    const float* attD = (const float*)d_in[5];
    const float* bg   = (const float*)d_in[6];

    // 1) gather all params into one staging buffer (1 tiny kernel node)
    pack_params<<<1, 256>>>(Wpre, bpre, Wg, attS, attD, bg);

    // 2) single D2D copy into the constant bank (1 memcpy node)
    void* dp = nullptr;
    cudaGetSymbolAddress(&dp, dPack);
    cudaMemcpyToSymbolAsync(cPack, dp, 840 * sizeof(float), 0, cudaMemcpyDeviceToDevice, 0);

    // 3) main kernel
    const int nodes  = in_sizes[0] / 3;   // 3,145,728
    const int blocks = nodes / NPB;       // 8,192 (exact)
    gat_encoder_kernel<<<blocks, TPB>>>(src, Wg, (float*)d_out);
}

// round 15
// speedup vs baseline: 1.1709x; 1.1233x over previous
#include <cuda_runtime.h>

#define NJ   24
#define TPB  192
#define NPB  (TPB * 2)     // 384 nodes = 16 frames per block; thread owns nodes t, t+192
#define RS   28            // sH row stride (floats): h[24] + a_src[3] + pad
#define NEG  0.2f

typedef unsigned long long ull;

__constant__ int c_parent[NJ] = {-1,0,0,0,1,2,3,4,5,6,7,8,9,9,9,12,13,14,16,17,18,19,20,21};
#define PARENT_MASK 0x3F73FFu   // joints that are some child's parent

__constant__ __align__(16) float cWg[576];   // Wg (24,24), one D2D memcpy node per launch

__device__ __forceinline__ void fma2(ull &d, ull a, ull b) {
    asm("fma.rn.f32x2 %0, %1, %2, %0;" : "+l"(d) : "l"(a), "l"(b));
}
__device__ __forceinline__ ull pack2(float x) {
    ull r; asm("mov.b64 %0, {%1, %1};" : "=l"(r) : "f"(x)); return r;
}
__device__ __forceinline__ ull packf2(float lo, float hi) {
    ull r; asm("mov.b64 %0, {%1, %2};" : "=l"(r) : "f"(lo), "f"(hi)); return r;
}
__device__ __forceinline__ float2 unpack2(ull v) {
    float2 f; asm("mov.b64 {%0, %1}, %2;" : "=f"(f.x), "=f"(f.y) : "l"(v)); return f;
}

// epilogue for one node: 2-edge softmax + aggregate + bias + relu + store
__device__ __forceinline__ void finish_node(const ull* __restrict__ acc,   // 12 ch-pairs
                                            const float* __restrict__ aS,  // [3]
                                            const float* __restrict__ aD,  // [3]
                                            const float* __restrict__ prow,
                                            bool hasPar,
                                            const ull* __restrict__ bgp,   // 12 bias pairs
                                            float* __restrict__ outp)
{
    const ulonglong2* p2 = (const ulonglong2*)prow;
    ulonglong2 pr[6];
    #pragma unroll
    for (int q = 0; q < 6; q++) pr[q] = p2[q];         // parent h as 12 ch-pairs
    const float pasv[3] = {prow[24], prow[25], prow[26]};

    float alS[3], alP[3];
    #pragma unroll
    for (int hh = 0; hh < 3; hh++) {
        float es = aS[hh] + aD[hh];
        es = es >= 0.0f ? es : NEG * es;
        float ep = pasv[hh] + aD[hh];
        ep = ep >= 0.0f ? ep : NEG * ep;
        ep = hasPar ? ep : -1e30f;
        const float mx  = fmaxf(es, ep);
        const float ws  = __expf(es - mx);
        const float wp  = __expf(ep - mx);
        const float inv = __fdividef(1.0f, ws + wp);
        alS[hh] = ws * inv;
        alP[hh] = hasPar ? wp * inv : 0.0f;
    }

    float4* o4 = (float4*)outp;
    #pragma unroll
    for (int v = 0; v < 6; v++) {                       // 2 ch-pairs per float4
        const int q0 = 2*v, q1 = 2*v + 1;
        const int hh = v >> 1;
        const ull s2 = pack2(alS[hh]);
        const ull p2k = pack2(alP[hh]);
        ull o0 = bgp[q0], o1 = bgp[q1];
        const ull ph0 = (q0 & 1) ? pr[q0 >> 1].y : pr[q0 >> 1].x;
        const ull ph1 = (q1 & 1) ? pr[q1 >> 1].y : pr[q1 >> 1].x;
        fma2(o0, s2, acc[q0]); fma2(o0, p2k, ph0);
        fma2(o1, s2, acc[q1]); fma2(o1, p2k, ph1);
        const float2 f0 = unpack2(o0), f1 = unpack2(o1);
        float4 r;
        r.x = fmaxf(f0.x, 0.f); r.y = fmaxf(f0.y, 0.f);
        r.z = fmaxf(f1.x, 0.f); r.w = fmaxf(f1.y, 0.f);
        o4[v] = r;
    }
}

__global__ __launch_bounds__(TPB, 4)
void gat_encoder_kernel(const float* __restrict__ src,
                        const float* __restrict__ Wpre,   // (3,24)
                        const float* __restrict__ bpre,   // (24)
                        const float* __restrict__ Wg,     // (24,24) for shared staging
                        const float* __restrict__ attS,   // (3,8)
                        const float* __restrict__ attD,   // (3,8)
                        const float* __restrict__ bg,     // (24)
                        float* __restrict__ out)
{
    __shared__ __align__(16) ull   sP2[96];       // per k: {w0,w0},{w1,w1},{w2,w2},{b,b}
    __shared__ __align__(16) float sWgL[24 * 4];  // Wg channels 0..3, 16B rows
    __shared__ __align__(16) float sAttS[24];
    __shared__ __align__(16) float sAttD[24];
    __shared__ __align__(16) float sbg[24];
    __shared__ __align__(16) float sH[NPB * RS];

    const int t = threadIdx.x;
    const int j = t % NJ;

    if (t < 96) {
        const int k = t >> 2, r = t & 3;
        const float v = (r < 3) ? Wpre[r * 24 + k] : bpre[k];
        sP2[k * 4 + r] = pack2(v);                 // pre-splatted x-chain table
        sWgL[t] = Wg[k * 24 + r];                  // Wg channels 0..3
    }
    if (t < 24) { sAttS[t] = attS[t]; sAttD[t] = attD[t]; sbg[t] = bg[t]; }

    const size_t base = (size_t)blockIdx.x * NPB;

    // ---- inputs: node pair (t, t+192) packed per input channel ----
    const float* pA = src + (base + (size_t)t) * 3;
    const float* pB = src + (base + (size_t)(t + TPB)) * 3;
    const float a0 = pA[0], a1 = pA[1], a2 = pA[2];
    const float b0 = pB[0], b1 = pB[1], b2 = pB[2];
    const ull pin0 = packf2(a0, b0);
    const ull pin1 = packf2(a1, b1);
    const ull pin2 = packf2(a2, b2);

    __syncthreads();

    // ---- fused: per k, x[k] for both nodes (one packed fma chain), feed 24-ch GEMM ----
    ull accA[12], accB[12];   // channel pairs for node t / node t+192
    #pragma unroll
    for (int q = 0; q < 12; q++) { accA[q] = 0ull; accB[q] = 0ull; }

    #pragma unroll
    for (int k = 0; k < 24; k++) {
        // x-chain: 2 LDS.128 of pre-splatted pairs
        const ulonglong2* pp = (const ulonglong2*)(sP2 + k * 4);
        const ulonglong2 p01 = pp[0], p23 = pp[1];
        ull xc = p23.y;                                // bias pair
        fma2(xc, pin0, p01.x);
        fma2(xc, pin1, p01.y);
        fma2(xc, pin2, p23.x);
        const float2 f = unpack2(xc);
        const ull xi = pack2(fmaxf(f.x, 0.0f));        // node t
        const ull xj = pack2(fmaxf(f.y, 0.0f));        // node t+192

        // Wg channels 0..3 from shared (1 LDS.128)
        const ulonglong2 w0 = *(const ulonglong2*)(sWgL + k * 4);
        // Wg channels 4..23 from constant (5 LDC.128, uniform path)
        const ulonglong2 w1 = *(const ulonglong2*)(cWg + k * 24 + 4);
        const ulonglong2 w2 = *(const ulonglong2*)(cWg + k * 24 + 8);
        const ulonglong2 w3 = *(const ulonglong2*)(cWg + k * 24 + 12);
        const ulonglong2 w4 = *(const ulonglong2*)(cWg + k * 24 + 16);
        const ulonglong2 w5 = *(const ulonglong2*)(cWg + k * 24 + 20);

        fma2(accA[0], xi, w0.x); fma2(accA[1], xi, w0.y);
        fma2(accA[2], xi, w1.x); fma2(accA[3], xi, w1.y);
        fma2(accB[0], xj, w0.x); fma2(accB[1], xj, w0.y);
        fma2(accB[2], xj, w1.x); fma2(accB[3], xj, w1.y);
        fma2(accA[4], xi, w2.x); fma2(accA[5], xi, w2.y);
        fma2(accA[6], xi, w3.x); fma2(accA[7], xi, w3.y);
        fma2(accB[4], xj, w2.x); fma2(accB[5], xj, w2.y);
        fma2(accB[6], xj, w3.x); fma2(accB[7], xj, w3.y);
        fma2(accA[8],  xi, w4.x); fma2(accA[9],  xi, w4.y);
        fma2(accA[10], xi, w5.x); fma2(accA[11], xi, w5.y);
        fma2(accB[8],  xj, w4.x); fma2(accB[9],  xj, w4.y);
        fma2(accB[10], xj, w5.x); fma2(accB[11], xj, w5.y);
    }

    // ---- attention dots, all 3 heads, both nodes ----
    float aSA[3], aDA[3], aSB[3], aDB[3];
    {
        const ulonglong2* S2 = (const ulonglong2*)sAttS;
        const ulonglong2* D2 = (const ulonglong2*)sAttD;
        #pragma unroll
        for (int hh = 0; hh < 3; hh++) {
            const ulonglong2 sa = S2[2*hh], sb = S2[2*hh + 1];
            const ulonglong2 da = D2[2*hh], db = D2[2*hh + 1];
            ull rSA = 0ull, rDA = 0ull, rSB = 0ull, rDB = 0ull;
            fma2(rSA, accA[4*hh],   sa.x); fma2(rSA, accA[4*hh+1], sa.y);
            fma2(rSA, accA[4*hh+2], sb.x); fma2(rSA, accA[4*hh+3], sb.y);
            fma2(rDA, accA[4*hh],   da.x); fma2(rDA, accA[4*hh+1], da.y);
            fma2(rDA, accA[4*hh+2], db.x); fma2(rDA, accA[4*hh+3], db.y);
            fma2(rSB, accB[4*hh],   sa.x); fma2(rSB, accB[4*hh+1], sa.y);
            fma2(rSB, accB[4*hh+2], sb.x); fma2(rSB, accB[4*hh+3], sb.y);
            fma2(rDB, accB[4*hh],   da.x); fma2(rDB, accB[4*hh+1], da.y);
            fma2(rDB, accB[4*hh+2], db.x); fma2(rDB, accB[4*hh+3], db.y);
            float2 f;
            f = unpack2(rSA); aSA[hh] = f.x + f.y;
            f = unpack2(rDA); aDA[hh] = f.x + f.y;
            f = unpack2(rSB); aSB[hh] = f.x + f.y;
            f = unpack2(rDB); aDB[hh] = f.x + f.y;
        }
    }

    // ---- publish h + a_src (only parent joints) ----
    if ((PARENT_MASK >> j) & 1u) {
        ulonglong2* r0 = (ulonglong2*)(sH + t * RS);
        ulonglong2* r1 = (ulonglong2*)(sH + (t + TPB) * RS);
        #pragma unroll
        for (int q = 0; q < 6; q++) {
            ulonglong2 va; va.x = accA[2*q]; va.y = accA[2*q + 1]; r0[q] = va;
            ulonglong2 vb; vb.x = accB[2*q]; vb.y = accB[2*q + 1]; r1[q] = vb;
        }
        float* f0 = sH + t * RS;
        float* f1 = sH + (t + TPB) * RS;
        f0[24] = aSA[0]; f0[25] = aSA[1]; f0[26] = aSA[2];
        f1[24] = aSB[0]; f1[25] = aSB[1]; f1[26] = aSB[2];
    }
    __syncthreads();

    // ---- epilogue ----
    const int par = c_parent[j];
    const bool hasPar = (par >= 0);
    const int pt = (t - j) + (hasPar ? par : j);

    ull bgp[12];
    {
        const ulonglong2* b2 = (const ulonglong2*)sbg;
        #pragma unroll
        for (int v = 0; v < 6; v++) { bgp[2*v] = b2[v].x; bgp[2*v + 1] = b2[v].y; }
    }

    finish_node(accA, aSA, aDA, sH + pt * RS,         hasPar, bgp, out + (base + (size_t)t) * 24);
    finish_node(accB, aSB, aDB, sH + (pt + TPB) * RS, hasPar, bgp, out + (base + (size_t)(t + TPB)) * 24);
}

extern "C" void kernel_launch(void* const* d_in, const int* in_sizes, int n_in,
                              void* d_out, int out_size) {
    (void)n_in; (void)out_size;
    const float* src  = (const float*)d_in[0];
    const float* Wpre = (const float*)d_in[1];
    const float* bpre = (const float*)d_in[2];
    const float* Wg   = (const float*)d_in[3];
    const float* attS = (const float*)d_in[4];
    const float* attD = (const float*)d_in[5];
    const float* bg   = (const float*)d_in[6];

    // single D2D memcpy node: Wg -> constant bank (R12-validated, ~zero overhead)
    cudaMemcpyToSymbolAsync(cWg, Wg, 576 * sizeof(float), 0, cudaMemcpyDeviceToDevice, 0);

    const int nodes  = in_sizes[0] / 3;   // 3,145,728
    const int blocks = nodes / NPB;       // 8,192 (exact)
    gat_encoder_kernel<<<blocks, TPB>>>(src, Wpre, bpre, Wg, attS, attD, bg, (float*)d_out);
}

// round 16
// speedup vs baseline: 1.2518x; 1.0691x over previous
#include <cuda_runtime.h>

#define NJ   24
#define TPB  192
#define NPB  (TPB * 2)     // 384 nodes = 16 frames per block; thread owns nodes t, t+192
#define RS   28            // sH row stride (floats): h[24] + a_src[3] + pad
#define NEG  0.2f

typedef unsigned long long ull;

__constant__ int c_parent[NJ] = {-1,0,0,0,1,2,3,4,5,6,7,8,9,9,9,12,13,14,16,17,18,19,20,21};
#define PARENT_MASK 0x3F73FFu   // joints that are some child's parent

__constant__ __align__(16) float cWg[576];   // Wg (24,24), one D2D memcpy node per launch

__device__ __forceinline__ void fma2(ull &d, ull a, ull b) {
    asm("fma.rn.f32x2 %0, %1, %2, %0;" : "+l"(d) : "l"(a), "l"(b));
}
__device__ __forceinline__ ull pack2(float x) {
    ull r; asm("mov.b64 %0, {%1, %1};" : "=l"(r) : "f"(x)); return r;
}
__device__ __forceinline__ ull packf2(float lo, float hi) {
    ull r; asm("mov.b64 %0, {%1, %2};" : "=l"(r) : "f"(lo), "f"(hi)); return r;
}
__device__ __forceinline__ float2 unpack2(ull v) {
    float2 f; asm("mov.b64 {%0, %1}, %2;" : "=f"(f.x), "=f"(f.y) : "l"(v)); return f;
}

// epilogue for one node: 2-edge softmax + aggregate + bias + relu + store
__device__ __forceinline__ void finish_node(const ull* __restrict__ acc,   // 12 ch-pairs
                                            const float* __restrict__ aS,  // [3]
                                            const float* __restrict__ aD,  // [3]
                                            const float* __restrict__ prow,
                                            bool hasPar,
                                            const ull* __restrict__ bgp,   // 12 bias pairs
                                            float* __restrict__ outp)
{
    const ulonglong2* p2 = (const ulonglong2*)prow;
    ulonglong2 pr[6];
    #pragma unroll
    for (int q = 0; q < 6; q++) pr[q] = p2[q];         // parent h as 12 ch-pairs
    const float pasv[3] = {prow[24], prow[25], prow[26]};

    float alS[3], alP[3];
    #pragma unroll
    for (int hh = 0; hh < 3; hh++) {
        float es = aS[hh] + aD[hh];
        es = es >= 0.0f ? es : NEG * es;
        float ep = pasv[hh] + aD[hh];
        ep = ep >= 0.0f ? ep : NEG * ep;
        ep = hasPar ? ep : -1e30f;
        const float mx  = fmaxf(es, ep);
        const float ws  = __expf(es - mx);
        const float wp  = __expf(ep - mx);
        const float inv = __fdividef(1.0f, ws + wp);
        alS[hh] = ws * inv;
        alP[hh] = hasPar ? wp * inv : 0.0f;
    }

    float4* o4 = (float4*)outp;
    #pragma unroll
    for (int v = 0; v < 6; v++) {                       // 2 ch-pairs per float4
        const int q0 = 2*v, q1 = 2*v + 1;
        const int hh = v >> 1;
        const ull s2 = pack2(alS[hh]);
        const ull p2k = pack2(alP[hh]);
        ull o0 = bgp[q0], o1 = bgp[q1];
        const ull ph0 = (q0 & 1) ? pr[q0 >> 1].y : pr[q0 >> 1].x;
        const ull ph1 = (q1 & 1) ? pr[q1 >> 1].y : pr[q1 >> 1].x;
        fma2(o0, s2, acc[q0]); fma2(o0, p2k, ph0);
        fma2(o1, s2, acc[q1]); fma2(o1, p2k, ph1);
        const float2 f0 = unpack2(o0), f1 = unpack2(o1);
        float4 r;
        r.x = fmaxf(f0.x, 0.f); r.y = fmaxf(f0.y, 0.f);
        r.z = fmaxf(f1.x, 0.f); r.w = fmaxf(f1.y, 0.f);
        o4[v] = r;
    }
}

__global__ __launch_bounds__(TPB, 4)
void gat_encoder_kernel(const float* __restrict__ src,
                        const float* __restrict__ Wpre,   // (3,24)
                        const float* __restrict__ bpre,   // (24)
                        const float* __restrict__ attS,   // (3,8)
                        const float* __restrict__ attD,   // (3,8)
                        const float* __restrict__ bg,     // (24)
                        float* __restrict__ out)
{
    __shared__ __align__(16) ull   sP2[96];       // per k: {w0,w0},{w1,w1},{w2,w2},{b,b}
    __shared__ __align__(16) float sAttS[24];
    __shared__ __align__(16) float sAttD[24];
    __shared__ __align__(16) float sbg[24];
    __shared__ __align__(16) float sH[NPB * RS];

    const int t = threadIdx.x;
    const int j = t % NJ;

    if (t < 96) {
        const int k = t >> 2, r = t & 3;
        const float v = (r < 3) ? Wpre[r * 24 + k] : bpre[k];
        sP2[k * 4 + r] = pack2(v);                 // pre-splatted x-chain table
    }
    if (t < 24) { sAttS[t] = attS[t]; sAttD[t] = attD[t]; sbg[t] = bg[t]; }

    const size_t base = (size_t)blockIdx.x * NPB;

    // ---- inputs: node pair (t, t+192) packed per input channel ----
    const float* pA = src + (base + (size_t)t) * 3;
    const float* pB = src + (base + (size_t)(t + TPB)) * 3;
    const float a0 = pA[0], a1 = pA[1], a2 = pA[2];
    const float b0 = pB[0], b1 = pB[1], b2 = pB[2];
    const ull pin0 = packf2(a0, b0);
    const ull pin1 = packf2(a1, b1);
    const ull pin2 = packf2(a2, b2);

    __syncthreads();

    // ---- fused: per k, x[k] for both nodes (one packed fma chain), feed 24-ch GEMM ----
    ull accA[12], accB[12];   // channel pairs for node t / node t+192
    #pragma unroll
    for (int q = 0; q < 12; q++) { accA[q] = 0ull; accB[q] = 0ull; }

    #pragma unroll
    for (int k = 0; k < 24; k++) {
        // x-chain: 2 LDS.128 of pre-splatted pairs
        const ulonglong2* pp = (const ulonglong2*)(sP2 + k * 4);
        const ulonglong2 p01 = pp[0], p23 = pp[1];
        ull xc = p23.y;                                // bias pair
        fma2(xc, pin0, p01.x);
        fma2(xc, pin1, p01.y);
        fma2(xc, pin2, p23.x);
        const float2 f = unpack2(xc);
        const ull xi = pack2(fmaxf(f.x, 0.0f));        // node t
        const ull xj = pack2(fmaxf(f.y, 0.0f));        // node t+192

        // all 24 Wg channels from the constant bank (6 LDC.128, uniform path)
        const ulonglong2 w0 = *(const ulonglong2*)(cWg + k * 24);
        const ulonglong2 w1 = *(const ulonglong2*)(cWg + k * 24 + 4);
        const ulonglong2 w2 = *(const ulonglong2*)(cWg + k * 24 + 8);
        const ulonglong2 w3 = *(const ulonglong2*)(cWg + k * 24 + 12);
        const ulonglong2 w4 = *(const ulonglong2*)(cWg + k * 24 + 16);
        const ulonglong2 w5 = *(const ulonglong2*)(cWg + k * 24 + 20);

        fma2(accA[0], xi, w0.x); fma2(accA[1], xi, w0.y);
        fma2(accA[2], xi, w1.x); fma2(accA[3], xi, w1.y);
        fma2(accB[0], xj, w0.x); fma2(accB[1], xj, w0.y);
        fma2(accB[2], xj, w1.x); fma2(accB[3], xj, w1.y);
        fma2(accA[4], xi, w2.x); fma2(accA[5], xi, w2.y);
        fma2(accA[6], xi, w3.x); fma2(accA[7], xi, w3.y);
        fma2(accB[4], xj, w2.x); fma2(accB[5], xj, w2.y);
        fma2(accB[6], xj, w3.x); fma2(accB[7], xj, w3.y);
        fma2(accA[8],  xi, w4.x); fma2(accA[9],  xi, w4.y);
        fma2(accA[10], xi, w5.x); fma2(accA[11], xi, w5.y);
        fma2(accB[8],  xj, w4.x); fma2(accB[9],  xj, w4.y);
        fma2(accB[10], xj, w5.x); fma2(accB[11], xj, w5.y);
    }

    // ---- attention dots, all 3 heads, both nodes ----
    float aSA[3], aDA[3], aSB[3], aDB[3];
    {
        const ulonglong2* S2 = (const ulonglong2*)sAttS;
        const ulonglong2* D2 = (const ulonglong2*)sAttD;
        #pragma unroll
        for (int hh = 0; hh < 3; hh++) {
            const ulonglong2 sa = S2[2*hh], sb = S2[2*hh + 1];
            const ulonglong2 da = D2[2*hh], db = D2[2*hh + 1];
            ull rSA = 0ull, rDA = 0ull, rSB = 0ull, rDB = 0ull;
            fma2(rSA, accA[4*hh],   sa.x); fma2(rSA, accA[4*hh+1], sa.y);
            fma2(rSA, accA[4*hh+2], sb.x); fma2(rSA, accA[4*hh+3], sb.y);
            fma2(rDA, accA[4*hh],   da.x); fma2(rDA, accA[4*hh+1], da.y);
            fma2(rDA, accA[4*hh+2], db.x); fma2(rDA, accA[4*hh+3], db.y);
            fma2(rSB, accB[4*hh],   sa.x); fma2(rSB, accB[4*hh+1], sa.y);
            fma2(rSB, accB[4*hh+2], sb.x); fma2(rSB, accB[4*hh+3], sb.y);
            fma2(rDB, accB[4*hh],   da.x); fma2(rDB, accB[4*hh+1], da.y);
            fma2(rDB, accB[4*hh+2], db.x); fma2(rDB, accB[4*hh+3], db.y);
            float2 f;
            f = unpack2(rSA); aSA[hh] = f.x + f.y;
            f = unpack2(rDA); aDA[hh] = f.x + f.y;
            f = unpack2(rSB); aSB[hh] = f.x + f.y;
            f = unpack2(rDB); aDB[hh] = f.x + f.y;
        }
    }

    // ---- publish h + a_src (only parent joints) ----
    if ((PARENT_MASK >> j) & 1u) {
        ulonglong2* r0 = (ulonglong2*)(sH + t * RS);
        ulonglong2* r1 = (ulonglong2*)(sH + (t + TPB) * RS);
        #pragma unroll
        for (int q = 0; q < 6; q++) {
            ulonglong2 va; va.x = accA[2*q]; va.y = accA[2*q + 1]; r0[q] = va;
            ulonglong2 vb; vb.x = accB[2*q]; vb.y = accB[2*q + 1]; r1[q] = vb;
        }
        float* f0 = sH + t * RS;
        float* f1 = sH + (t + TPB) * RS;
        f0[24] = aSA[0]; f0[25] = aSA[1]; f0[26] = aSA[2];
        f1[24] = aSB[0]; f1[25] = aSB[1]; f1[26] = aSB[2];
    }
    __syncthreads();

    // ---- epilogue ----
    const int par = c_parent[j];
    const bool hasPar = (par >= 0);
    const int pt = (t - j) + (hasPar ? par : j);

    ull bgp[12];
    {
        const ulonglong2* b2 = (const ulonglong2*)sbg;
        #pragma unroll
        for (int v = 0; v < 6; v++) { bgp[2*v] = b2[v].x; bgp[2*v + 1] = b2[v].y; }
    }

    finish_node(accA, aSA, aDA, sH + pt * RS,         hasPar, bgp, out + (base + (size_t)t) * 24);
    finish_node(accB, aSB, aDB, sH + (pt + TPB) * RS, hasPar, bgp, out + (base + (size_t)(t + TPB)) * 24);
}

extern "C" void kernel_launch(void* const* d_in, const int* in_sizes, int n_in,
                              void* d_out, int out_size) {
    (void)n_in; (void)out_size;
    const float* src  = (const float*)d_in[0];
    const float* Wpre = (const float*)d_in[1];
    const float* bpre = (const float*)d_in[2];
    const float* Wg   = (const float*)d_in[3];
    const float* attS = (const float*)d_in[4];
    const float* attD = (const float*)d_in[5];
    const float* bg   = (const float*)d_in[6];

    // single D2D memcpy node: Wg -> constant bank (validated ~zero overhead)
    cudaMemcpyToSymbolAsync(cWg, Wg, 576 * sizeof(float), 0, cudaMemcpyDeviceToDevice, 0);

    const int nodes  = in_sizes[0] / 3;   // 3,145,728
    const int blocks = nodes / NPB;       // 8,192 (exact)
    gat_encoder_kernel<<<blocks, TPB>>>(src, Wpre, bpre, attS, attD, bg, (float*)d_out);
}